// round 1
// baseline (speedup 1.0000x reference)
#include <cuda_runtime.h>
#include <cuda_bf16.h>
#include <math.h>

// ---------------- problem constants ----------------
#define BB 2
#define HH 128
#define WW 128
#define CC 256
#define WF 65            // W/2 + 1
#define NPIX 16384       // H*W
#define TT 32768         // B*H*W tokens
#define NBK 16           // AFNO blocks
#define BSZ 16           // AFNO block size
#define HID 128          // BS*EXP
#define HEADS 8
#define DH 32
#define TWO_PI 6.283185307179586476925286766559f

// ---------------- scratch (device globals; no allocs allowed) ----------------
__device__ float g_ln1[TT * CC];
__device__ float g_fr[BB * HH * WF * CC];
__device__ float g_fi[BB * HH * WF * CC];
__device__ float g_hr[BB * HH * WF * CC];
__device__ float g_hi[BB * HH * WF * CC];
__device__ float g_x1[TT * CC];
__device__ float g_ln2[TT * CC];
__device__ float g_q[TT * CC];
__device__ float g_k[TT * CC];
__device__ float g_v[TT * CC];
__device__ float g_kvpart[32 * 2 * 8 * 1024];
__device__ float g_kv[2 * 8 * 32 * 32];
__device__ float g_attn[TT * CC];
__device__ float g_x2[TT * CC];
__device__ float g_ln3[TT * CC];
__device__ float g_ffnh[TT * 2048];

// ---------------- helpers ----------------
__device__ __forceinline__ float wred32(float s) {
#pragma unroll
    for (int o = 16; o; o >>= 1) s += __shfl_xor_sync(0xffffffffu, s, o);
    return s;
}

__device__ __forceinline__ float gelu_f(float v) {
    return 0.5f * v * (1.0f + erff(v * 0.70710678118654752440f));
}

// ---------------- LayerNorm over last dim = 256 ----------------
// one warp per row; 8 rows per block
__global__ __launch_bounds__(256) void ln256_kernel(
    const float* __restrict__ x, const float* __restrict__ g,
    const float* __restrict__ b, float* __restrict__ out)
{
    int warp = threadIdx.x >> 5, lane = threadIdx.x & 31;
    size_t row = (size_t)blockIdx.x * 8 + warp;
    const float* xr = x + row * CC + (size_t)lane * 8;
    float v[8];
    float4 a0 = *(const float4*)(xr);
    float4 a1 = *(const float4*)(xr + 4);
    v[0]=a0.x; v[1]=a0.y; v[2]=a0.z; v[3]=a0.w;
    v[4]=a1.x; v[5]=a1.y; v[6]=a1.z; v[7]=a1.w;
    float s = 0.f;
#pragma unroll
    for (int i = 0; i < 8; ++i) s += v[i];
    s = wred32(s);
    float mu = s * (1.0f / 256.0f);
    float sq = 0.f;
#pragma unroll
    for (int i = 0; i < 8; ++i) { float d = v[i] - mu; sq += d * d; }
    sq = wred32(sq);
    float rs = rsqrtf(sq * (1.0f / 256.0f) + 1e-5f);
    int c = lane * 8;
    float4 g0 = *(const float4*)(g + c), g1 = *(const float4*)(g + c + 4);
    float4 b0 = *(const float4*)(b + c), b1 = *(const float4*)(b + c + 4);
    float4 o0, o1;
    o0.x=(v[0]-mu)*rs*g0.x+b0.x; o0.y=(v[1]-mu)*rs*g0.y+b0.y;
    o0.z=(v[2]-mu)*rs*g0.z+b0.z; o0.w=(v[3]-mu)*rs*g0.w+b0.w;
    o1.x=(v[4]-mu)*rs*g1.x+b1.x; o1.y=(v[5]-mu)*rs*g1.y+b1.y;
    o1.z=(v[6]-mu)*rs*g1.z+b1.z; o1.w=(v[7]-mu)*rs*g1.w+b1.w;
    *(float4*)(out + row * CC + c) = o0;
    *(float4*)(out + row * CC + c + 4) = o1;
}

// ---------------- rfft along W (DFT, ortho 1/128 applied here) ----------------
// grid: (B*H, 4 channel-tiles of 64); block 256 = 64c x 4 k-groups
__global__ __launch_bounds__(256) void fftw_kernel(
    const float* __restrict__ in, float* __restrict__ outr, float* __restrict__ outi)
{
    __shared__ float xs[128][64];
    __shared__ float twc[128], tws[128];
    int tid = threadIdx.x;
    int bh = blockIdx.x;
    int c0 = blockIdx.y * 64;
    if (tid < 128) {
        float s, c; sincosf(TWO_PI * tid * (1.0f / 128.0f), &s, &c);
        twc[tid] = c; tws[tid] = s;
    }
    const float* src = in + (size_t)bh * (WW * CC) + c0;
    for (int idx = tid; idx < 128 * 64; idx += 256) {
        int w = idx >> 6, cl = idx & 63;
        xs[w][cl] = src[(size_t)w * CC + cl];
    }
    __syncthreads();
    int cl = tid & 63, kg = tid >> 6;
    size_t obase = (size_t)bh * (WF * CC) + c0 + cl;
    for (int kq = kg; kq < WF; kq += 4) {
        float ar = 0.f, ai = 0.f;
        int t = 0;
        for (int w = 0; w < 128; ++w) {
            float xv = xs[w][cl];
            ar += xv * twc[t];
            ai -= xv * tws[t];
            t = (t + kq) & 127;
        }
        outr[obase + (size_t)kq * CC] = ar * (1.0f / 128.0f);
        outi[obase + (size_t)kq * CC] = ai * (1.0f / 128.0f);
    }
}

// ---------------- full complex DFT along H (sign=-1 fwd, +1 inv) ----------------
// grid: (B*65, 8 channel-tiles of 32); block 256 = 32c x 8 k-groups
__global__ __launch_bounds__(256) void ffth_kernel(
    const float* __restrict__ inr, const float* __restrict__ ini,
    float* __restrict__ outr, float* __restrict__ outi, float sign)
{
    __shared__ float xr[128 * 32], xi[128 * 32];
    __shared__ float twc[128], tws[128];
    int tid = threadIdx.x;
    int b = blockIdx.x / WF, wk = blockIdx.x % WF;
    int c0 = blockIdx.y * 32;
    if (tid < 128) {
        float s, c; sincosf(TWO_PI * tid * (1.0f / 128.0f), &s, &c);
        twc[tid] = c; tws[tid] = sign * s;
    }
    size_t base = (size_t)b * (HH * WF * CC) + (size_t)wk * CC + c0;
    for (int idx = tid; idx < 128 * 32; idx += 256) {
        int h = idx >> 5, cl = idx & 31;
        xr[idx] = inr[base + (size_t)h * (WF * CC) + cl];
        xi[idx] = ini[base + (size_t)h * (WF * CC) + cl];
    }
    __syncthreads();
    int cl = tid & 31, kg = tid >> 5;
    for (int kq = kg; kq < 128; kq += 8) {
        float ar = 0.f, ai = 0.f;
        int t = 0;
        for (int h = 0; h < 128; ++h) {
            float c = twc[t], s = tws[t];
            float r = xr[(h << 5) + cl], m = xi[(h << 5) + cl];
            ar += r * c - m * s;
            ai += r * s + m * c;
            t = (t + kq) & 127;
        }
        outr[base + (size_t)kq * (WF * CC) + cl] = ar;
        outi[base + (size_t)kq * (WF * CC) + cl] = ai;
    }
}

// ---------------- AFNO block MLP (complex 16->128->16) + softshrink ----------------
// grid: (16640/128 = 130 position tiles, 16 blocks n); block 128, one position per thread
__global__ __launch_bounds__(128) void afno_kernel(
    const float* __restrict__ inr, const float* __restrict__ ini,
    float* __restrict__ outr, float* __restrict__ outi,
    const float* __restrict__ w1, const float* __restrict__ b1,
    const float* __restrict__ w2, const float* __restrict__ b2)
{
    __shared__ float w1r[16 * 128], w1i[16 * 128];
    __shared__ float w2r[128 * 16], w2i[128 * 16];
    __shared__ float b1r[128], b1i[128], b2r[16], b2i[16];
    int tid = threadIdx.x;
    int n = blockIdx.y;
    const float* w1r_g = w1 + (size_t)n * 2048;
    const float* w1i_g = w1 + 32768 + (size_t)n * 2048;
    const float* w2r_g = w2 + (size_t)n * 2048;
    const float* w2i_g = w2 + 32768 + (size_t)n * 2048;
    for (int i = tid; i < 2048; i += 128) {
        w1r[i] = w1r_g[i]; w1i[i] = w1i_g[i];
        w2r[i] = w2r_g[i]; w2i[i] = w2i_g[i];
    }
    b1r[tid] = b1[(size_t)n * 128 + tid];
    b1i[tid] = b1[2048 + (size_t)n * 128 + tid];
    if (tid < 16) {
        b2r[tid] = b2[(size_t)n * 16 + tid];
        b2i[tid] = b2[256 + (size_t)n * 16 + tid];
    }
    __syncthreads();

    int pos = blockIdx.x * 128 + tid;  // flat over (b,h,wk): 0..16639
    size_t base = (size_t)pos * CC + n * 16;
    float xr[16], xi[16];
#pragma unroll
    for (int i = 0; i < 16; i += 4) {
        float4 r4 = *(const float4*)(inr + base + i);
        float4 i4 = *(const float4*)(ini + base + i);
        xr[i]=r4.x; xr[i+1]=r4.y; xr[i+2]=r4.z; xr[i+3]=r4.w;
        xi[i]=i4.x; xi[i+1]=i4.y; xi[i+2]=i4.z; xi[i+3]=i4.w;
    }
    float or_[16], oi_[16];
#pragma unroll
    for (int o = 0; o < 16; ++o) { or_[o] = 0.f; oi_[o] = 0.f; }

#pragma unroll 2
    for (int j = 0; j < 128; ++j) {
        float hr = b1r[j], hi = b1i[j];
#pragma unroll
        for (int i = 0; i < 16; ++i) {
            float wr = w1r[i * 128 + j], wi = w1i[i * 128 + j];
            hr += xr[i] * wr - xi[i] * wi;
            hi += xi[i] * wr + xr[i] * wi;
        }
        hr = fmaxf(hr, 0.f); hi = fmaxf(hi, 0.f);
#pragma unroll
        for (int o = 0; o < 16; ++o) {
            float wr = w2r[j * 16 + o], wi = w2i[j * 16 + o];
            or_[o] += hr * wr - hi * wi;
            oi_[o] += hi * wr + hr * wi;
        }
    }
#pragma unroll
    for (int o = 0; o < 16; ++o) {
        float vr = or_[o] + b2r[o];
        float vi = oi_[o] + b2i[o];
        vr = copysignf(fmaxf(fabsf(vr) - 0.01f, 0.f), vr);
        vi = copysignf(fmaxf(fabsf(vi) - 0.01f, 0.f), vi);
        or_[o] = vr; oi_[o] = vi;
    }
#pragma unroll
    for (int i = 0; i < 16; i += 4) {
        float4 r4 = make_float4(or_[i], or_[i+1], or_[i+2], or_[i+3]);
        float4 i4 = make_float4(oi_[i], oi_[i+1], oi_[i+2], oi_[i+3]);
        *(float4*)(outr + base + i) = r4;
        *(float4*)(outi + base + i) = i4;
    }
}

// ---------------- irfft along W + residual: out = x + ln1 + irfft ----------------
// c2r convention: imag of DC and Nyquist bins ignored. grid (B*H, 4 c-tiles), block 256
__global__ __launch_bounds__(256) void irfftw_kernel(
    const float* __restrict__ inr, const float* __restrict__ ini,
    const float* __restrict__ xin, const float* __restrict__ ln1,
    float* __restrict__ out)
{
    __shared__ float Xr[WF][64], Xi[WF][64];
    __shared__ float twc[128], tws[128];
    int tid = threadIdx.x;
    int bh = blockIdx.x;
    int c0 = blockIdx.y * 64;
    if (tid < 128) {
        float s, c; sincosf(TWO_PI * tid * (1.0f / 128.0f), &s, &c);
        twc[tid] = c; tws[tid] = s;
    }
    size_t ibase = (size_t)bh * (WF * CC) + c0;
    for (int idx = tid; idx < WF * 64; idx += 256) {
        int kk = idx >> 6, cl = idx & 63;
        Xr[kk][cl] = inr[ibase + (size_t)kk * CC + cl];
        Xi[kk][cl] = ini[ibase + (size_t)kk * CC + cl];
    }
    __syncthreads();
    int cl = tid & 63, wg = tid >> 6;
    float x0 = Xr[0][cl], xn = Xr[64][cl];
    for (int w = wg; w < 128; w += 4) {
        float s = 0.f;
        int t = w;
#pragma unroll 7
        for (int kq = 1; kq <= 63; ++kq) {
            s += Xr[kq][cl] * twc[t] - Xi[kq][cl] * tws[t];
            t = (t + w) & 127;
        }
        float val = x0 + ((w & 1) ? -xn : xn) + 2.f * s;
        size_t o = (size_t)bh * (WW * CC) + (size_t)w * CC + c0 + cl;
        out[o] = xin[o] + ln1[o] + val * (1.0f / 128.0f);
    }
}

// ---------------- fp32 GEMM: C = act(A[M,K] @ W[N,K]^T + bias) (+ Res) ----------------
// 128x128x8 tile, 256 threads, 8x8 per thread
template <int ACT, int RES>
__global__ __launch_bounds__(256) void gemm_kernel(
    const float* __restrict__ A, const float* __restrict__ Wt,
    const float* __restrict__ bias, const float* __restrict__ Res,
    float* __restrict__ C, int M, int N, int K)
{
    __shared__ float As[8][136];
    __shared__ float Bs[8][136];
    int tid = threadIdx.x;
    int m0 = blockIdx.x * 128, n0 = blockIdx.y * 128;
    int tm = tid >> 4, tn = tid & 15;
    float acc[8][8];
#pragma unroll
    for (int i = 0; i < 8; ++i)
#pragma unroll
        for (int j = 0; j < 8; ++j) acc[i][j] = 0.f;

    for (int k0 = 0; k0 < K; k0 += 8) {
        __syncthreads();
#pragma unroll
        for (int l = 0; l < 4; ++l) {
            int idx = tid + l * 256;
            int r = idx >> 3, kk = idx & 7;
            As[kk][r] = A[(size_t)(m0 + r) * K + k0 + kk];
            Bs[kk][r] = Wt[(size_t)(n0 + r) * K + k0 + kk];
        }
        __syncthreads();
#pragma unroll
        for (int kk = 0; kk < 8; ++kk) {
            float a[8], bf[8];
            *(float4*)&a[0]  = *(const float4*)&As[kk][tm * 8];
            *(float4*)&a[4]  = *(const float4*)&As[kk][tm * 8 + 4];
            *(float4*)&bf[0] = *(const float4*)&Bs[kk][tn * 8];
            *(float4*)&bf[4] = *(const float4*)&Bs[kk][tn * 8 + 4];
#pragma unroll
            for (int i = 0; i < 8; ++i)
#pragma unroll
                for (int j = 0; j < 8; ++j)
                    acc[i][j] += a[i] * bf[j];
        }
    }
#pragma unroll
    for (int i = 0; i < 8; ++i) {
        size_t m = m0 + tm * 8 + i;
#pragma unroll
        for (int j = 0; j < 8; j += 4) {
            int n = n0 + tn * 8 + j;
            float4 o;
            float* po = &o.x;
#pragma unroll
            for (int u = 0; u < 4; ++u) {
                float vv = acc[i][j + u] + bias[n + u];
                if (ACT == 1) vv = gelu_f(vv);
                po[u] = vv;
            }
            if (RES) {
                float4 rr = *(const float4*)&Res[m * N + n];
                o.x += rr.x; o.y += rr.y; o.z += rr.z; o.w += rr.w;
            }
            *(float4*)&C[m * N + n] = o;
        }
    }
}

// ---------------- per-head LN on k and v (dh=32) ----------------
__global__ __launch_bounds__(256) void headln_kernel(
    float* __restrict__ k, float* __restrict__ v,
    const float* __restrict__ kg, const float* __restrict__ kb,
    const float* __restrict__ vg, const float* __restrict__ vb)
{
    int warp = threadIdx.x >> 5, lane = threadIdx.x & 31;
    size_t t = (size_t)blockIdx.x * 8 + warp;
#pragma unroll
    for (int head = 0; head < 8; ++head) {
        int c = head * 32 + lane;
        size_t idx = t * CC + c;
        {
            float val = k[idx];
            float mu = wred32(val) * (1.0f / 32.0f);
            float d = val - mu;
            float var = wred32(d * d) * (1.0f / 32.0f);
            float rs = rsqrtf(var + 1e-5f);
            k[idx] = d * rs * kg[c] + kb[c];
        }
        {
            float val = v[idx];
            float mu = wred32(val) * (1.0f / 32.0f);
            float d = val - mu;
            float var = wred32(d * d) * (1.0f / 32.0f);
            float rs = rsqrtf(var + 1e-5f);
            v[idx] = d * rs * vg[c] + vb[c];
        }
    }
}

// ---------------- kv partial outer-products (deterministic two-stage) ----------------
// grid (32 chunks, 8 heads, 2 batch); block 256; 512 tokens per block
__global__ __launch_bounds__(256) void kvpart_kernel(
    const float* __restrict__ k, const float* __restrict__ v, float* __restrict__ part)
{
    __shared__ float ks[32][32], vs[32][32];
    int tid = threadIdx.x;
    int chunk = blockIdx.x, head = blockIdx.y, b = blockIdx.z;
    int d = tid >> 3, e0 = (tid & 7) * 4;
    float a0 = 0.f, a1 = 0.f, a2 = 0.f, a3 = 0.f;
    int t0 = b * NPIX + chunk * 512;
    for (int gq = 0; gq < 16; ++gq) {
        __syncthreads();
        for (int idx = tid; idx < 1024; idx += 256) {
            int ttk = idx >> 5, dd = idx & 31;
            size_t off = (size_t)(t0 + gq * 32 + ttk) * CC + head * 32 + dd;
            ks[ttk][dd] = k[off];
            vs[ttk][dd] = v[off];
        }
        __syncthreads();
#pragma unroll
        for (int ttk = 0; ttk < 32; ++ttk) {
            float kd = ks[ttk][d];
            float4 ve = *(const float4*)&vs[ttk][e0];
            a0 += kd * ve.x; a1 += kd * ve.y; a2 += kd * ve.z; a3 += kd * ve.w;
        }
    }
    size_t o = ((size_t)(chunk * 2 + b) * 8 + head) * 1024 + d * 32 + e0;
    part[o] = a0; part[o + 1] = a1; part[o + 2] = a2; part[o + 3] = a3;
}

__global__ __launch_bounds__(256) void kvreduce_kernel(
    const float* __restrict__ part, float* __restrict__ kv)
{
    int f = blockIdx.x * 256 + threadIdx.x;  // 16384 outputs
    float s = 0.f;
#pragma unroll
    for (int ch = 0; ch < 32; ++ch) s += part[(size_t)ch * 16384 + f];
    kv[f] = s * (1.0f / (float)NPIX);
}

// ---------------- attn out = q @ kv ----------------
// grid T/8; block 256; 8 tokens per block
__global__ __launch_bounds__(256) void attn_kernel(
    const float* __restrict__ q, const float* __restrict__ kv, float* __restrict__ out)
{
    __shared__ float kvs[8192];
    __shared__ float qs[8 * 256];
    int tid = threadIdx.x;
    int t0 = blockIdx.x * 8;
    int b = t0 >> 14;
    for (int i = tid; i < 8192; i += 256) kvs[i] = kv[(size_t)b * 8192 + i];
    for (int i = tid; i < 2048; i += 256) qs[i] = q[(size_t)t0 * CC + i];
    __syncthreads();
    int head = tid >> 5, e = tid & 31;
#pragma unroll
    for (int ttk = 0; ttk < 8; ++ttk) {
        float acc = 0.f;
#pragma unroll
        for (int dd = 0; dd < 32; ++dd)
            acc += qs[ttk * 256 + head * 32 + dd] * kvs[(head * 32 + dd) * 32 + e];
        out[(size_t)(t0 + ttk) * CC + tid] = acc;
    }
}

// ---------------- launch ----------------
extern "C" void kernel_launch(void* const* d_in, const int* in_sizes, int n_in,
                              void* d_out, int out_size)
{
    const float* x       = (const float*)d_in[0];
    const float* afno_w1 = (const float*)d_in[1];
    const float* afno_b1 = (const float*)d_in[2];
    const float* afno_w2 = (const float*)d_in[3];
    const float* afno_b2 = (const float*)d_in[4];
    const float* wq = (const float*)d_in[5];  const float* bq = (const float*)d_in[6];
    const float* wk = (const float*)d_in[7];  const float* bk = (const float*)d_in[8];
    const float* wv = (const float*)d_in[9];  const float* bv = (const float*)d_in[10];
    const float* lnkg = (const float*)d_in[11]; const float* lnkb = (const float*)d_in[12];
    const float* lnvg = (const float*)d_in[13]; const float* lnvb = (const float*)d_in[14];
    const float* wo = (const float*)d_in[15]; const float* bo = (const float*)d_in[16];
    const float* wup = (const float*)d_in[17]; const float* bup = (const float*)d_in[18];
    const float* wdn = (const float*)d_in[19]; const float* bdn = (const float*)d_in[20];
    const float* n1g = (const float*)d_in[21]; const float* n1b = (const float*)d_in[22];
    const float* n2g = (const float*)d_in[23]; const float* n2b = (const float*)d_in[24];
    const float* n3g = (const float*)d_in[25]; const float* n3b = (const float*)d_in[26];
    float* out = (float*)d_out;

    float *ln1, *fr, *fi, *hr, *hi, *x1, *ln2, *q, *k, *v, *kvp, *kv, *attn, *x2, *ln3, *ffnh;
    cudaGetSymbolAddress((void**)&ln1, g_ln1);
    cudaGetSymbolAddress((void**)&fr,  g_fr);
    cudaGetSymbolAddress((void**)&fi,  g_fi);
    cudaGetSymbolAddress((void**)&hr,  g_hr);
    cudaGetSymbolAddress((void**)&hi,  g_hi);
    cudaGetSymbolAddress((void**)&x1,  g_x1);
    cudaGetSymbolAddress((void**)&ln2, g_ln2);
    cudaGetSymbolAddress((void**)&q,   g_q);
    cudaGetSymbolAddress((void**)&k,   g_k);
    cudaGetSymbolAddress((void**)&v,   g_v);
    cudaGetSymbolAddress((void**)&kvp, g_kvpart);
    cudaGetSymbolAddress((void**)&kv,  g_kv);
    cudaGetSymbolAddress((void**)&attn,g_attn);
    cudaGetSymbolAddress((void**)&x2,  g_x2);
    cudaGetSymbolAddress((void**)&ln3, g_ln3);
    cudaGetSymbolAddress((void**)&ffnh,g_ffnh);

    // 1) LN1
    ln256_kernel<<<TT / 8, 256>>>(x, n1g, n1b, ln1);
    // 2) AFNO spectral path
    fftw_kernel<<<dim3(BB * HH, 4), 256>>>(ln1, fr, fi);
    ffth_kernel<<<dim3(BB * WF, 8), 256>>>(fr, fi, hr, hi, -1.0f);
    afno_kernel<<<dim3(130, NBK), 128>>>(hr, hi, fr, fi, afno_w1, afno_b1, afno_w2, afno_b2);
    ffth_kernel<<<dim3(BB * WF, 8), 256>>>(fr, fi, hr, hi, +1.0f);
    irfftw_kernel<<<dim3(BB * HH, 4), 256>>>(hr, hi, x, ln1, x1);
    // 3) Galerkin attention
    ln256_kernel<<<TT / 8, 256>>>(x1, n2g, n2b, ln2);
    gemm_kernel<0, 0><<<dim3(TT / 128, 2), 256>>>(ln2, wq, bq, nullptr, q, TT, CC, CC);
    gemm_kernel<0, 0><<<dim3(TT / 128, 2), 256>>>(ln2, wk, bk, nullptr, k, TT, CC, CC);
    gemm_kernel<0, 0><<<dim3(TT / 128, 2), 256>>>(ln2, wv, bv, nullptr, v, TT, CC, CC);
    headln_kernel<<<TT / 8, 256>>>(k, v, lnkg, lnkb, lnvg, lnvb);
    kvpart_kernel<<<dim3(32, HEADS, BB), 256>>>(k, v, kvp);
    kvreduce_kernel<<<64, 256>>>(kvp, kv);
    attn_kernel<<<TT / 8, 256>>>(q, kv, attn);
    gemm_kernel<0, 1><<<dim3(TT / 128, 2), 256>>>(attn, wo, bo, ln2, x2, TT, CC, CC);
    // 4) FFN
    ln256_kernel<<<TT / 8, 256>>>(x2, n3g, n3b, ln3);
    gemm_kernel<1, 0><<<dim3(TT / 128, 16), 256>>>(ln3, wup, bup, nullptr, ffnh, TT, 2048, CC);
    gemm_kernel<0, 1><<<dim3(TT / 128, 2), 256>>>(ffnh, wdn, bdn, ln3, out, TT, CC, 2048);
}

// round 4
// speedup vs baseline: 1.5691x; 1.5691x over previous
#include <cuda_runtime.h>
#include <cuda_bf16.h>
#include <math.h>
#include <stdint.h>

// ---------------- problem constants ----------------
#define BB 2
#define HH 128
#define WW 128
#define CC 256
#define WF 65            // W/2 + 1
#define NPIX 16384       // H*W
#define TT 32768         // B*H*W tokens
#define NBK 16           // AFNO blocks
#define HEADS 8
#define TWO_PI 6.283185307179586476925286766559f

// ---------------- scratch (device globals; no allocs allowed) ----------------
__device__ float g_ln1[TT * CC];
__device__ float g_fr[BB * HH * WF * CC];
__device__ float g_fi[BB * HH * WF * CC];
__device__ float g_hr[BB * HH * WF * CC];
__device__ float g_hi[BB * HH * WF * CC];
__device__ float g_x1[TT * CC];
__device__ float g_ln2[TT * CC];
__device__ float g_q[TT * CC];
__device__ float g_k[TT * CC];
__device__ float g_v[TT * CC];
__device__ float g_kvpart[32 * 2 * 8 * 1024];
__device__ float g_kv[2 * 8 * 32 * 32];
__device__ float g_x2[TT * CC];
__device__ float g_ln3[TT * CC];
// bf16 hi/lo operand buffers
__device__ __nv_bfloat16 g_ah[TT * CC];
__device__ __nv_bfloat16 g_al[TT * CC];
__device__ __nv_bfloat16 g_fh[TT * 2048];
__device__ __nv_bfloat16 g_fl[TT * 2048];
__device__ __nv_bfloat16 g_wh[1310720];   // wq,wk,wv,wo (65536 each), wup(524288), wdn(524288)
__device__ __nv_bfloat16 g_wl[1310720];

// ---------------- small helpers ----------------
__device__ __forceinline__ float wred32(float s) {
#pragma unroll
    for (int o = 16; o; o >>= 1) s += __shfl_xor_sync(0xffffffffu, s, o);
    return s;
}
__device__ __forceinline__ float gelu_f(float v) {
    return 0.5f * v * (1.0f + erff(v * 0.70710678118654752440f));
}
__device__ __forceinline__ void split2(float v, __nv_bfloat16& h, __nv_bfloat16& l) {
    h = __float2bfloat16(v);
    l = __float2bfloat16(v - __bfloat162float(h));
}

// mma.sync m16n8k16 row.col f32 += bf16*bf16
__device__ __forceinline__ void mma16816(float* c, const uint32_t* a, const uint32_t* b) {
    asm volatile(
        "mma.sync.aligned.m16n8k16.row.col.f32.bf16.bf16.f32 "
        "{%0,%1,%2,%3}, {%4,%5,%6,%7}, {%8,%9}, {%0,%1,%2,%3};"
        : "+f"(c[0]), "+f"(c[1]), "+f"(c[2]), "+f"(c[3])
        : "r"(a[0]), "r"(a[1]), "r"(a[2]), "r"(a[3]), "r"(b[0]), "r"(b[1]));
}

// ---------------- fp32 -> bf16 hi/lo split ----------------
__global__ __launch_bounds__(256) void split_kernel(
    const float* __restrict__ in, __nv_bfloat16* __restrict__ hi,
    __nv_bfloat16* __restrict__ lo, int n4)
{
    int i = blockIdx.x * 256 + threadIdx.x;
    if (i >= n4) return;
    float4 v = ((const float4*)in)[i];
    __nv_bfloat16 h0, h1, h2, h3, l0, l1, l2, l3;
    split2(v.x, h0, l0); split2(v.y, h1, l1); split2(v.z, h2, l2); split2(v.w, h3, l3);
    ((__nv_bfloat162*)hi)[2 * i]     = __nv_bfloat162(h0, h1);
    ((__nv_bfloat162*)hi)[2 * i + 1] = __nv_bfloat162(h2, h3);
    ((__nv_bfloat162*)lo)[2 * i]     = __nv_bfloat162(l0, l1);
    ((__nv_bfloat162*)lo)[2 * i + 1] = __nv_bfloat162(l2, l3);
}

// ---------------- LayerNorm over last dim = 256 (+ optional bf16 hi/lo) --------
template <int SPLIT>
__global__ __launch_bounds__(256) void ln256_kernel(
    const float* __restrict__ x, const float* __restrict__ g,
    const float* __restrict__ b, float* __restrict__ out,
    __nv_bfloat16* __restrict__ oh, __nv_bfloat16* __restrict__ ol)
{
    int warp = threadIdx.x >> 5, lane = threadIdx.x & 31;
    size_t row = (size_t)blockIdx.x * 8 + warp;
    const float* xr = x + row * CC + (size_t)lane * 8;
    float v[8];
    float4 a0 = *(const float4*)(xr);
    float4 a1 = *(const float4*)(xr + 4);
    v[0]=a0.x; v[1]=a0.y; v[2]=a0.z; v[3]=a0.w;
    v[4]=a1.x; v[5]=a1.y; v[6]=a1.z; v[7]=a1.w;
    float s = 0.f;
#pragma unroll
    for (int i = 0; i < 8; ++i) s += v[i];
    s = wred32(s);
    float mu = s * (1.0f / 256.0f);
    float sq = 0.f;
#pragma unroll
    for (int i = 0; i < 8; ++i) { float d = v[i] - mu; sq += d * d; }
    sq = wred32(sq);
    float rs = rsqrtf(sq * (1.0f / 256.0f) + 1e-5f);
    int c = lane * 8;
    float4 g0 = *(const float4*)(g + c), g1 = *(const float4*)(g + c + 4);
    float4 b0 = *(const float4*)(b + c), b1 = *(const float4*)(b + c + 4);
    float o[8];
    o[0]=(v[0]-mu)*rs*g0.x+b0.x; o[1]=(v[1]-mu)*rs*g0.y+b0.y;
    o[2]=(v[2]-mu)*rs*g0.z+b0.z; o[3]=(v[3]-mu)*rs*g0.w+b0.w;
    o[4]=(v[4]-mu)*rs*g1.x+b1.x; o[5]=(v[5]-mu)*rs*g1.y+b1.y;
    o[6]=(v[6]-mu)*rs*g1.z+b1.z; o[7]=(v[7]-mu)*rs*g1.w+b1.w;
    *(float4*)(out + row * CC + c)     = make_float4(o[0], o[1], o[2], o[3]);
    *(float4*)(out + row * CC + c + 4) = make_float4(o[4], o[5], o[6], o[7]);
    if (SPLIT) {
#pragma unroll
        for (int i = 0; i < 8; i += 2) {
            __nv_bfloat16 h0, h1, l0, l1;
            split2(o[i], h0, l0); split2(o[i + 1], h1, l1);
            *(__nv_bfloat162*)(oh + row * CC + c + i) = __nv_bfloat162(h0, h1);
            *(__nv_bfloat162*)(ol + row * CC + c + i) = __nv_bfloat162(l0, l1);
        }
    }
}

// ---------------- rfft along W ----------------
__global__ __launch_bounds__(256) void fftw_kernel(
    const float* __restrict__ in, float* __restrict__ outr, float* __restrict__ outi)
{
    __shared__ float xs[128][64];
    __shared__ float twc[128], tws[128];
    int tid = threadIdx.x;
    int bh = blockIdx.x;
    int c0 = blockIdx.y * 64;
    if (tid < 128) {
        float s, c; sincosf(TWO_PI * tid * (1.0f / 128.0f), &s, &c);
        twc[tid] = c; tws[tid] = s;
    }
    const float* src = in + (size_t)bh * (WW * CC) + c0;
    for (int idx = tid; idx < 128 * 64; idx += 256) {
        int w = idx >> 6, cl = idx & 63;
        xs[w][cl] = src[(size_t)w * CC + cl];
    }
    __syncthreads();
    int cl = tid & 63, kg = tid >> 6;
    size_t obase = (size_t)bh * (WF * CC) + c0 + cl;
    for (int kq = kg; kq < WF; kq += 4) {
        float ar = 0.f, ai = 0.f;
        int t = 0;
        for (int w = 0; w < 128; ++w) {
            float xv = xs[w][cl];
            ar += xv * twc[t];
            ai -= xv * tws[t];
            t = (t + kq) & 127;
        }
        outr[obase + (size_t)kq * CC] = ar * (1.0f / 128.0f);
        outi[obase + (size_t)kq * CC] = ai * (1.0f / 128.0f);
    }
}

// ---------------- full complex DFT along H ----------------
__global__ __launch_bounds__(256) void ffth_kernel(
    const float* __restrict__ inr, const float* __restrict__ ini,
    float* __restrict__ outr, float* __restrict__ outi, float sign)
{
    __shared__ float xr[128 * 32], xi[128 * 32];
    __shared__ float twc[128], tws[128];
    int tid = threadIdx.x;
    int b = blockIdx.x / WF, wk = blockIdx.x % WF;
    int c0 = blockIdx.y * 32;
    if (tid < 128) {
        float s, c; sincosf(TWO_PI * tid * (1.0f / 128.0f), &s, &c);
        twc[tid] = c; tws[tid] = sign * s;
    }
    size_t base = (size_t)b * (HH * WF * CC) + (size_t)wk * CC + c0;
    for (int idx = tid; idx < 128 * 32; idx += 256) {
        int h = idx >> 5, cl = idx & 31;
        xr[idx] = inr[base + (size_t)h * (WF * CC) + cl];
        xi[idx] = ini[base + (size_t)h * (WF * CC) + cl];
    }
    __syncthreads();
    int cl = tid & 31, kg = tid >> 5;
    for (int kq = kg; kq < 128; kq += 8) {
        float ar = 0.f, ai = 0.f;
        int t = 0;
        for (int h = 0; h < 128; ++h) {
            float c = twc[t], s = tws[t];
            float r = xr[(h << 5) + cl], m = xi[(h << 5) + cl];
            ar += r * c - m * s;
            ai += r * s + m * c;
            t = (t + kq) & 127;
        }
        outr[base + (size_t)kq * (WF * CC) + cl] = ar;
        outi[base + (size_t)kq * (WF * CC) + cl] = ai;
    }
}

// ---------------- AFNO block MLP ----------------
__global__ __launch_bounds__(128) void afno_kernel(
    const float* __restrict__ inr, const float* __restrict__ ini,
    float* __restrict__ outr, float* __restrict__ outi,
    const float* __restrict__ w1, const float* __restrict__ b1,
    const float* __restrict__ w2, const float* __restrict__ b2)
{
    __shared__ float w1r[16 * 128], w1i[16 * 128];
    __shared__ float w2r[128 * 16], w2i[128 * 16];
    __shared__ float b1r[128], b1i[128], b2r[16], b2i[16];
    int tid = threadIdx.x;
    int n = blockIdx.y;
    const float* w1r_g = w1 + (size_t)n * 2048;
    const float* w1i_g = w1 + 32768 + (size_t)n * 2048;
    const float* w2r_g = w2 + (size_t)n * 2048;
    const float* w2i_g = w2 + 32768 + (size_t)n * 2048;
    for (int i = tid; i < 2048; i += 128) {
        w1r[i] = w1r_g[i]; w1i[i] = w1i_g[i];
        w2r[i] = w2r_g[i]; w2i[i] = w2i_g[i];
    }
    b1r[tid] = b1[(size_t)n * 128 + tid];
    b1i[tid] = b1[2048 + (size_t)n * 128 + tid];
    if (tid < 16) {
        b2r[tid] = b2[(size_t)n * 16 + tid];
        b2i[tid] = b2[256 + (size_t)n * 16 + tid];
    }
    __syncthreads();

    int pos = blockIdx.x * 128 + tid;
    size_t base = (size_t)pos * CC + n * 16;
    float xr[16], xi[16];
#pragma unroll
    for (int i = 0; i < 16; i += 4) {
        float4 r4 = *(const float4*)(inr + base + i);
        float4 i4 = *(const float4*)(ini + base + i);
        xr[i]=r4.x; xr[i+1]=r4.y; xr[i+2]=r4.z; xr[i+3]=r4.w;
        xi[i]=i4.x; xi[i+1]=i4.y; xi[i+2]=i4.z; xi[i+3]=i4.w;
    }
    float or_[16], oi_[16];
#pragma unroll
    for (int o = 0; o < 16; ++o) { or_[o] = 0.f; oi_[o] = 0.f; }

#pragma unroll 2
    for (int j = 0; j < 128; ++j) {
        float hr = b1r[j], hi = b1i[j];
#pragma unroll
        for (int i = 0; i < 16; ++i) {
            float wr = w1r[i * 128 + j], wi = w1i[i * 128 + j];
            hr += xr[i] * wr - xi[i] * wi;
            hi += xi[i] * wr + xr[i] * wi;
        }
        hr = fmaxf(hr, 0.f); hi = fmaxf(hi, 0.f);
#pragma unroll
        for (int o = 0; o < 16; ++o) {
            float wr = w2r[j * 16 + o], wi = w2i[j * 16 + o];
            or_[o] += hr * wr - hi * wi;
            oi_[o] += hi * wr + hr * wi;
        }
    }
#pragma unroll
    for (int o = 0; o < 16; ++o) {
        float vr = or_[o] + b2r[o];
        float vi = oi_[o] + b2i[o];
        vr = copysignf(fmaxf(fabsf(vr) - 0.01f, 0.f), vr);
        vi = copysignf(fmaxf(fabsf(vi) - 0.01f, 0.f), vi);
        or_[o] = vr; oi_[o] = vi;
    }
#pragma unroll
    for (int i = 0; i < 16; i += 4) {
        *(float4*)(outr + base + i) = make_float4(or_[i], or_[i+1], or_[i+2], or_[i+3]);
        *(float4*)(outi + base + i) = make_float4(oi_[i], oi_[i+1], oi_[i+2], oi_[i+3]);
    }
}

// ---------------- irfft along W + residual ----------------
__global__ __launch_bounds__(256) void irfftw_kernel(
    const float* __restrict__ inr, const float* __restrict__ ini,
    const float* __restrict__ xin, const float* __restrict__ ln1,
    float* __restrict__ out)
{
    __shared__ float Xr[WF][64], Xi[WF][64];
    __shared__ float twc[128], tws[128];
    int tid = threadIdx.x;
    int bh = blockIdx.x;
    int c0 = blockIdx.y * 64;
    if (tid < 128) {
        float s, c; sincosf(TWO_PI * tid * (1.0f / 128.0f), &s, &c);
        twc[tid] = c; tws[tid] = s;
    }
    size_t ibase = (size_t)bh * (WF * CC) + c0;
    for (int idx = tid; idx < WF * 64; idx += 256) {
        int kk = idx >> 6, cl = idx & 63;
        Xr[kk][cl] = inr[ibase + (size_t)kk * CC + cl];
        Xi[kk][cl] = ini[ibase + (size_t)kk * CC + cl];
    }
    __syncthreads();
    int cl = tid & 63, wg = tid >> 6;
    float x0 = Xr[0][cl], xn = Xr[64][cl];
    for (int w = wg; w < 128; w += 4) {
        float s = 0.f;
        int t = w;
#pragma unroll 7
        for (int kq = 1; kq <= 63; ++kq) {
            s += Xr[kq][cl] * twc[t] - Xi[kq][cl] * tws[t];
            t = (t + w) & 127;
        }
        float val = x0 + ((w & 1) ? -xn : xn) + 2.f * s;
        size_t o = (size_t)bh * (WW * CC) + (size_t)w * CC + c0 + cl;
        out[o] = xin[o] + ln1[o] + val * (1.0f / 128.0f);
    }
}

// ---------------- mma.sync GEMM: C[M,N] = act(A@W^T + bias) (+Res) ----------------
// A: [M,KTOT] bf16 hi/lo, W: [N,KTOT] bf16 hi/lo. BM=128, BN=128, BK=32.
// 8 warps: 2(m) x 4(n), warp tile 64x32. 3-MMA hi/lo split.
template <int KTOT, int ACT, int RES, int OUTBF>
__global__ __launch_bounds__(256) void gemm_mma(
    const __nv_bfloat16* __restrict__ Ah, const __nv_bfloat16* __restrict__ Al,
    const __nv_bfloat16* __restrict__ Wh, const __nv_bfloat16* __restrict__ Wl,
    const float* __restrict__ bias, const float* __restrict__ Resp,
    float* __restrict__ Cf, __nv_bfloat16* __restrict__ Ch, __nv_bfloat16* __restrict__ Cl,
    int NT)
{
    __shared__ __nv_bfloat16 sAh[128][40], sAl[128][40], sWh[128][40], sWl[128][40];
    int tid = threadIdx.x, lane = tid & 31, wid = tid >> 5;
    int mw = wid & 1, nw = wid >> 1;
    int m0 = blockIdx.x * 128, n0 = blockIdx.y * 128;
    int g = lane >> 2, t = lane & 3;

    float acc[4][4][4];
#pragma unroll
    for (int i = 0; i < 4; ++i)
#pragma unroll
        for (int j = 0; j < 4; ++j)
#pragma unroll
            for (int r = 0; r < 4; ++r) acc[i][j][r] = 0.f;

    for (int k0 = 0; k0 < KTOT; k0 += 32) {
#pragma unroll
        for (int s0 = 0; s0 < 512; s0 += 256) {
            int s = s0 + tid;
            int r = s >> 2, cs = (s & 3) * 8;
            *(uint4*)&sAh[r][cs] = *(const uint4*)(Ah + (size_t)(m0 + r) * KTOT + k0 + cs);
            *(uint4*)&sAl[r][cs] = *(const uint4*)(Al + (size_t)(m0 + r) * KTOT + k0 + cs);
            *(uint4*)&sWh[r][cs] = *(const uint4*)(Wh + (size_t)(n0 + r) * KTOT + k0 + cs);
            *(uint4*)&sWl[r][cs] = *(const uint4*)(Wl + (size_t)(n0 + r) * KTOT + k0 + cs);
        }
        __syncthreads();
#pragma unroll
        for (int ks = 0; ks < 2; ++ks) {
            int kk = ks * 16;
            uint32_t ah[4][4], al[4][4];
#pragma unroll
            for (int i = 0; i < 4; ++i) {
                int r0 = mw * 64 + i * 16 + g;
                ah[i][0] = *(const uint32_t*)&sAh[r0][kk + 2 * t];
                ah[i][1] = *(const uint32_t*)&sAh[r0 + 8][kk + 2 * t];
                ah[i][2] = *(const uint32_t*)&sAh[r0][kk + 8 + 2 * t];
                ah[i][3] = *(const uint32_t*)&sAh[r0 + 8][kk + 8 + 2 * t];
                al[i][0] = *(const uint32_t*)&sAl[r0][kk + 2 * t];
                al[i][1] = *(const uint32_t*)&sAl[r0 + 8][kk + 2 * t];
                al[i][2] = *(const uint32_t*)&sAl[r0][kk + 8 + 2 * t];
                al[i][3] = *(const uint32_t*)&sAl[r0 + 8][kk + 8 + 2 * t];
            }
#pragma unroll
            for (int j = 0; j < 4; ++j) {
                int n = nw * 32 + j * 8 + g;
                uint32_t bh[2], bl[2];
                bh[0] = *(const uint32_t*)&sWh[n][kk + 2 * t];
                bh[1] = *(const uint32_t*)&sWh[n][kk + 8 + 2 * t];
                bl[0] = *(const uint32_t*)&sWl[n][kk + 2 * t];
                bl[1] = *(const uint32_t*)&sWl[n][kk + 8 + 2 * t];
#pragma unroll
                for (int i = 0; i < 4; ++i) {
                    mma16816(acc[i][j], ah[i], bh);
                    mma16816(acc[i][j], al[i], bh);
                    mma16816(acc[i][j], ah[i], bl);
                }
            }
        }
        __syncthreads();
    }

    // epilogue: direct stores; each thread owns pairs of consecutive columns
#pragma unroll
    for (int i = 0; i < 4; ++i) {
        int r0 = m0 + mw * 64 + i * 16 + g;
#pragma unroll
        for (int j = 0; j < 4; ++j) {
            int cb = n0 + nw * 32 + j * 8 + 2 * t;
            float bb0 = bias[cb], bb1 = bias[cb + 1];
#pragma unroll
            for (int hf = 0; hf < 2; ++hf) {
                int r = r0 + hf * 8;
                float v0 = acc[i][j][hf * 2 + 0] + bb0;
                float v1 = acc[i][j][hf * 2 + 1] + bb1;
                if (ACT) { v0 = gelu_f(v0); v1 = gelu_f(v1); }
                size_t gi = (size_t)r * NT + cb;
                if (RES) {
                    float2 rr = *(const float2*)&Resp[gi];
                    v0 += rr.x; v1 += rr.y;
                }
                if (OUTBF) {
                    __nv_bfloat16 h0, l0, h1, l1;
                    split2(v0, h0, l0); split2(v1, h1, l1);
                    *(__nv_bfloat162*)&Ch[gi] = __nv_bfloat162(h0, h1);
                    *(__nv_bfloat162*)&Cl[gi] = __nv_bfloat162(l0, l1);
                } else {
                    *(float2*)&Cf[gi] = make_float2(v0, v1);
                }
            }
        }
    }
}

// ---------------- per-head LN on k and v (dh=32) ----------------
__global__ __launch_bounds__(256) void headln_kernel(
    float* __restrict__ k, float* __restrict__ v,
    const float* __restrict__ kg, const float* __restrict__ kb,
    const float* __restrict__ vg, const float* __restrict__ vb)
{
    int warp = threadIdx.x >> 5, lane = threadIdx.x & 31;
    size_t t = (size_t)blockIdx.x * 8 + warp;
#pragma unroll
    for (int head = 0; head < 8; ++head) {
        int c = head * 32 + lane;
        size_t idx = t * CC + c;
        {
            float val = k[idx];
            float mu = wred32(val) * (1.0f / 32.0f);
            float d = val - mu;
            float var = wred32(d * d) * (1.0f / 32.0f);
            k[idx] = d * rsqrtf(var + 1e-5f) * kg[c] + kb[c];
        }
        {
            float val = v[idx];
            float mu = wred32(val) * (1.0f / 32.0f);
            float d = val - mu;
            float var = wred32(d * d) * (1.0f / 32.0f);
            v[idx] = d * rsqrtf(var + 1e-5f) * vg[c] + vb[c];
        }
    }
}

// ---------------- kv partial outer-products ----------------
__global__ __launch_bounds__(256) void kvpart_kernel(
    const float* __restrict__ k, const float* __restrict__ v, float* __restrict__ part)
{
    __shared__ float ks[32][32], vs[32][32];
    int tid = threadIdx.x;
    int chunk = blockIdx.x, head = blockIdx.y, b = blockIdx.z;
    int d = tid >> 3, e0 = (tid & 7) * 4;
    float a0 = 0.f, a1 = 0.f, a2 = 0.f, a3 = 0.f;
    int t0 = b * NPIX + chunk * 512;
    for (int gq = 0; gq < 16; ++gq) {
        __syncthreads();
        for (int idx = tid; idx < 1024; idx += 256) {
            int ttk = idx >> 5, dd = idx & 31;
            size_t off = (size_t)(t0 + gq * 32 + ttk) * CC + head * 32 + dd;
            ks[ttk][dd] = k[off];
            vs[ttk][dd] = v[off];
        }
        __syncthreads();
#pragma unroll
        for (int ttk = 0; ttk < 32; ++ttk) {
            float kd = ks[ttk][d];
            float4 ve = *(const float4*)&vs[ttk][e0];
            a0 += kd * ve.x; a1 += kd * ve.y; a2 += kd * ve.z; a3 += kd * ve.w;
        }
    }
    size_t o = ((size_t)(chunk * 2 + b) * 8 + head) * 1024 + d * 32 + e0;
    part[o] = a0; part[o + 1] = a1; part[o + 2] = a2; part[o + 3] = a3;
}

__global__ __launch_bounds__(256) void kvreduce_kernel(
    const float* __restrict__ part, float* __restrict__ kv)
{
    int f = blockIdx.x * 256 + threadIdx.x;
    float s = 0.f;
#pragma unroll
    for (int ch = 0; ch < 32; ++ch) s += part[(size_t)ch * 16384 + f];
    kv[f] = s * (1.0f / (float)NPIX);
}

// ---------------- attn out = q @ kv; writes bf16 hi/lo directly ----------------
__global__ __launch_bounds__(256) void attn_kernel(
    const float* __restrict__ q, const float* __restrict__ kv,
    __nv_bfloat16* __restrict__ oh, __nv_bfloat16* __restrict__ ol)
{
    __shared__ float kvs[8192];
    __shared__ float qs[8 * 256];
    int tid = threadIdx.x;
    int t0 = blockIdx.x * 8;
    int b = t0 >> 14;
    for (int i = tid; i < 8192; i += 256) kvs[i] = kv[(size_t)b * 8192 + i];
    for (int i = tid; i < 2048; i += 256) qs[i] = q[(size_t)t0 * CC + i];
    __syncthreads();
    int head = tid >> 5, e = tid & 31;
#pragma unroll
    for (int ttk = 0; ttk < 8; ++ttk) {
        float acc = 0.f;
#pragma unroll
        for (int dd = 0; dd < 32; ++dd)
            acc += qs[ttk * 256 + head * 32 + dd] * kvs[(head * 32 + dd) * 32 + e];
        __nv_bfloat16 h, l;
        split2(acc, h, l);
        size_t gi = (size_t)(t0 + ttk) * CC + tid;
        oh[gi] = h; ol[gi] = l;
    }
}

// ---------------- launch ----------------
extern "C" void kernel_launch(void* const* d_in, const int* in_sizes, int n_in,
                              void* d_out, int out_size)
{
    const float* x       = (const float*)d_in[0];
    const float* afno_w1 = (const float*)d_in[1];
    const float* afno_b1 = (const float*)d_in[2];
    const float* afno_w2 = (const float*)d_in[3];
    const float* afno_b2 = (const float*)d_in[4];
    const float* wq = (const float*)d_in[5];  const float* bq = (const float*)d_in[6];
    const float* wk = (const float*)d_in[7];  const float* bk = (const float*)d_in[8];
    const float* wv = (const float*)d_in[9];  const float* bv = (const float*)d_in[10];
    const float* lnkg = (const float*)d_in[11]; const float* lnkb = (const float*)d_in[12];
    const float* lnvg = (const float*)d_in[13]; const float* lnvb = (const float*)d_in[14];
    const float* wo = (const float*)d_in[15]; const float* bo = (const float*)d_in[16];
    const float* wup = (const float*)d_in[17]; const float* bup = (const float*)d_in[18];
    const float* wdn = (const float*)d_in[19]; const float* bdn = (const float*)d_in[20];
    const float* n1g = (const float*)d_in[21]; const float* n1b = (const float*)d_in[22];
    const float* n2g = (const float*)d_in[23]; const float* n2b = (const float*)d_in[24];
    const float* n3g = (const float*)d_in[25]; const float* n3b = (const float*)d_in[26];
    float* out = (float*)d_out;

    float *ln1, *fr, *fi, *hr, *hi, *x1, *ln2, *q, *k, *v, *kvp, *kv, *x2, *ln3;
    __nv_bfloat16 *ah, *al, *fh, *fl, *wh, *wl;
    cudaGetSymbolAddress((void**)&ln1, g_ln1);
    cudaGetSymbolAddress((void**)&fr,  g_fr);
    cudaGetSymbolAddress((void**)&fi,  g_fi);
    cudaGetSymbolAddress((void**)&hr,  g_hr);
    cudaGetSymbolAddress((void**)&hi,  g_hi);
    cudaGetSymbolAddress((void**)&x1,  g_x1);
    cudaGetSymbolAddress((void**)&ln2, g_ln2);
    cudaGetSymbolAddress((void**)&q,   g_q);
    cudaGetSymbolAddress((void**)&k,   g_k);
    cudaGetSymbolAddress((void**)&v,   g_v);
    cudaGetSymbolAddress((void**)&kvp, g_kvpart);
    cudaGetSymbolAddress((void**)&kv,  g_kv);
    cudaGetSymbolAddress((void**)&x2,  g_x2);
    cudaGetSymbolAddress((void**)&ln3, g_ln3);
    cudaGetSymbolAddress((void**)&ah,  g_ah);
    cudaGetSymbolAddress((void**)&al,  g_al);
    cudaGetSymbolAddress((void**)&fh,  g_fh);
    cudaGetSymbolAddress((void**)&fl,  g_fl);
    cudaGetSymbolAddress((void**)&wh,  g_wh);
    cudaGetSymbolAddress((void**)&wl,  g_wl);

    // weight splits (fp32 -> bf16 hi/lo)
    split_kernel<<<64, 256>>>(wq,  wh,           wl,           16384);
    split_kernel<<<64, 256>>>(wk,  wh + 65536,   wl + 65536,   16384);
    split_kernel<<<64, 256>>>(wv,  wh + 131072,  wl + 131072,  16384);
    split_kernel<<<64, 256>>>(wo,  wh + 196608,  wl + 196608,  16384);
    split_kernel<<<512, 256>>>(wup, wh + 262144, wl + 262144,  131072);
    split_kernel<<<512, 256>>>(wdn, wh + 786432, wl + 786432,  131072);

    // 1) LN1 + AFNO spectral block
    ln256_kernel<0><<<TT / 8, 256>>>(x, n1g, n1b, ln1, nullptr, nullptr);
    fftw_kernel<<<dim3(BB * HH, 4), 256>>>(ln1, fr, fi);
    ffth_kernel<<<dim3(BB * WF, 8), 256>>>(fr, fi, hr, hi, -1.0f);
    afno_kernel<<<dim3(130, NBK), 128>>>(hr, hi, fr, fi, afno_w1, afno_b1, afno_w2, afno_b2);
    ffth_kernel<<<dim3(BB * WF, 8), 256>>>(fr, fi, hr, hi, +1.0f);
    irfftw_kernel<<<dim3(BB * HH, 4), 256>>>(hr, hi, x, ln1, x1);

    // 2) Galerkin attention block
    ln256_kernel<1><<<TT / 8, 256>>>(x1, n2g, n2b, ln2, ah, al);
    gemm_mma<256, 0, 0, 0><<<dim3(256, 2), 256>>>(ah, al, wh, wl, bq, nullptr, q, nullptr, nullptr, CC);
    gemm_mma<256, 0, 0, 0><<<dim3(256, 2), 256>>>(ah, al, wh + 65536, wl + 65536, bk, nullptr, k, nullptr, nullptr, CC);
    gemm_mma<256, 0, 0, 0><<<dim3(256, 2), 256>>>(ah, al, wh + 131072, wl + 131072, bv, nullptr, v, nullptr, nullptr, CC);
    headln_kernel<<<TT / 8, 256>>>(k, v, lnkg, lnkb, lnvg, lnvb);
    kvpart_kernel<<<dim3(32, HEADS, BB), 256>>>(k, v, kvp);
    kvreduce_kernel<<<64, 256>>>(kvp, kv);
    attn_kernel<<<TT / 8, 256>>>(q, kv, ah, al);
    gemm_mma<256, 0, 1, 0><<<dim3(256, 2), 256>>>(ah, al, wh + 196608, wl + 196608, bo, ln2, x2, nullptr, nullptr, CC);

    // 3) FFN block
    ln256_kernel<1><<<TT / 8, 256>>>(x2, n3g, n3b, ln3, ah, al);
    gemm_mma<256, 1, 0, 1><<<dim3(256, 16), 256>>>(ah, al, wh + 262144, wl + 262144, bup, nullptr, nullptr, fh, fl, 2048);
    gemm_mma<2048, 0, 1, 0><<<dim3(256, 2), 256>>>(fh, fl, wh + 786432, wl + 786432, bdn, ln3, out, nullptr, nullptr, CC);
}